// round 1
// baseline (speedup 1.0000x reference)
#include <cuda_runtime.h>
#include <math.h>

// Problem shape (fixed for this problem)
#define B_  2
#define T_  2048
#define D_  1024
#define H_  16
#define HD_ 64
#define M_  (B_*T_)   // 4096 tokens total

// Scratch (allocation-free rule: __device__ globals)
__device__ float g_Q[(size_t)M_ * D_];
__device__ float g_K[(size_t)M_ * D_];
__device__ float g_V[(size_t)M_ * D_];
__device__ float g_C[(size_t)M_ * D_];

// ---------------------------------------------------------------------------
// SGEMM: C[M,N] = A[M,K] @ W[K,N] (+ bias). 128x128 block tile, BK=8,
// 256 threads, 8x8 register tile per thread. M,N % 128 == 0, K % 8 == 0.
// ---------------------------------------------------------------------------
__global__ void __launch_bounds__(256, 2) sgemm_kernel(
    const float* __restrict__ A, const float* __restrict__ W,
    const float* __restrict__ bias, float* __restrict__ C,
    int M, int N, int K)
{
    __shared__ float As[8][128];   // transposed A tile: As[k][row]
    __shared__ float Bs[8][128];   // Bs[k][col]

    const int tid = threadIdx.x;
    const int tx  = tid & 15;      // 0..15 -> 8 output cols each
    const int ty  = tid >> 4;      // 0..15 -> 8 output rows each
    const int bm  = blockIdx.y << 7;
    const int bn  = blockIdx.x << 7;

    // A-tile load mapping: 128 rows x 8 k -> 256 float4 (one per thread)
    const int arow = tid >> 1;
    const int ak   = (tid & 1) << 2;
    // B-tile load mapping: 8 k-rows x 128 cols -> 256 float4
    const int bk   = tid >> 5;
    const int bc   = (tid & 31) << 2;

    const float* Ap = A + (size_t)(bm + arow) * K + ak;
    const float* Wp = W + (size_t)bk * N + bn + bc;

    float acc[8][8];
#pragma unroll
    for (int i = 0; i < 8; i++)
#pragma unroll
        for (int j = 0; j < 8; j++) acc[i][j] = 0.f;

    for (int k0 = 0; k0 < K; k0 += 8) {
        float4 av = *(const float4*)(Ap + k0);
        float4 wv = *(const float4*)(Wp + (size_t)k0 * N);
        As[ak + 0][arow] = av.x;
        As[ak + 1][arow] = av.y;
        As[ak + 2][arow] = av.z;
        As[ak + 3][arow] = av.w;
        *(float4*)&Bs[bk][bc] = wv;
        __syncthreads();

#pragma unroll
        for (int kk = 0; kk < 8; kk++) {
            float a[8], b[8];
            *(float4*)&a[0] = *(const float4*)&As[kk][ty * 8];
            *(float4*)&a[4] = *(const float4*)&As[kk][ty * 8 + 4];
            *(float4*)&b[0] = *(const float4*)&Bs[kk][tx * 8];
            *(float4*)&b[4] = *(const float4*)&Bs[kk][tx * 8 + 4];
#pragma unroll
            for (int i = 0; i < 8; i++)
#pragma unroll
                for (int j = 0; j < 8; j++)
                    acc[i][j] = fmaf(a[i], b[j], acc[i][j]);
        }
        __syncthreads();
    }

#pragma unroll
    for (int i = 0; i < 8; i++) {
        float* Cp = C + (size_t)(bm + ty * 8 + i) * N + bn + tx * 8;
        float out[8];
#pragma unroll
        for (int j = 0; j < 8; j++) {
            out[j] = acc[i][j];
            if (bias) out[j] += bias[bn + tx * 8 + j];
        }
        *(float4*)&Cp[0] = *(float4*)&out[0];
        *(float4*)&Cp[4] = *(float4*)&out[4];
    }
}

// ---------------------------------------------------------------------------
// Flash attention (causal, online softmax).
// Block: one 64-query tile of one (b,h). 128 threads = (tx 0..7) x (ty 0..15).
// Thread computes a 4(row) x 8(col) fragment of S and of O.
// Q,K,V,C layouts: [B*T, D] row-major, head h occupies cols [h*64, h*64+64).
// Q pre-scaled by 1/sqrt(HD) = 0.125 at load (mask-then-scale equivalent:
// (-inf)/8 == -inf).
// ---------------------------------------------------------------------------
#define FSQ 65   // padded stride for Qs/Ks/Ps (bank-conflict avoidance)
#define FSV 64   // V stride (row-major, float4-friendly)
#define FLASH_SMEM ((3 * 64 * FSQ + 64 * FSV) * 4)

__global__ void __launch_bounds__(128) flash_kernel(
    const float* __restrict__ Q, const float* __restrict__ K,
    const float* __restrict__ V, float* __restrict__ O)
{
    extern __shared__ float sm[];
    float* Qs = sm;                  // [64][FSQ]
    float* Ks = Qs + 64 * FSQ;       // [64][FSQ]
    float* Ps = Ks + 64 * FSQ;       // [64][FSQ]
    float* Vs = Ps + 64 * FSQ;       // [64][FSV]

    const int qt  = blockIdx.x;          // query tile (0..31)
    const int bh  = blockIdx.y;          // b*H + h
    const int b   = bh >> 4;
    const int h   = bh & 15;
    const int tid = threadIdx.x;
    const int tx  = tid & 7;
    const int ty  = tid >> 3;

    const size_t base = ((size_t)b * T_) * D_ + (size_t)h * HD_;

    // Load Q tile (64x64), coalesced: idx -> (row = idx/16, d = (idx%16)*4)
#pragma unroll
    for (int i = 0; i < 8; i++) {
        int idx = tid + (i << 7);
        int r = idx >> 4;
        int d = (idx & 15) << 2;
        float4 v = *(const float4*)(Q + base + (size_t)(qt * 64 + r) * D_ + d);
        float* p = &Qs[r * FSQ + d];
        p[0] = v.x * 0.125f; p[1] = v.y * 0.125f;
        p[2] = v.z * 0.125f; p[3] = v.w * 0.125f;
    }

    float o[4][8];
    float m[4], l[4];
#pragma unroll
    for (int i = 0; i < 4; i++) {
        m[i] = -INFINITY; l[i] = 0.f;
#pragma unroll
        for (int j = 0; j < 8; j++) o[i][j] = 0.f;
    }

    for (int kt = 0; kt <= qt; kt++) {
        __syncthreads();  // protect Ks/Vs/Ps from previous iteration's readers
#pragma unroll
        for (int i = 0; i < 8; i++) {
            int idx = tid + (i << 7);
            int r = idx >> 4;
            int d = (idx & 15) << 2;
            const size_t g = base + (size_t)(kt * 64 + r) * D_ + d;
            float4 kv = *(const float4*)(K + g);
            float* pk = &Ks[r * FSQ + d];
            pk[0] = kv.x; pk[1] = kv.y; pk[2] = kv.z; pk[3] = kv.w;
            *(float4*)&Vs[r * FSV + d] = *(const float4*)(V + g);
        }
        __syncthreads();

        // S = Qs @ Ks^T fragment (4x8)
        float s[4][8];
#pragma unroll
        for (int i = 0; i < 4; i++)
#pragma unroll
            for (int j = 0; j < 8; j++) s[i][j] = 0.f;

#pragma unroll 4
        for (int d = 0; d < 64; d++) {
            float a0 = Qs[(ty * 4 + 0) * FSQ + d];
            float a1 = Qs[(ty * 4 + 1) * FSQ + d];
            float a2 = Qs[(ty * 4 + 2) * FSQ + d];
            float a3 = Qs[(ty * 4 + 3) * FSQ + d];
            float bb[8];
#pragma unroll
            for (int j = 0; j < 8; j++) bb[j] = Ks[(tx * 8 + j) * FSQ + d];
#pragma unroll
            for (int j = 0; j < 8; j++) {
                s[0][j] = fmaf(a0, bb[j], s[0][j]);
                s[1][j] = fmaf(a1, bb[j], s[1][j]);
                s[2][j] = fmaf(a2, bb[j], s[2][j]);
                s[3][j] = fmaf(a3, bb[j], s[3][j]);
            }
        }

        // Causal mask on the diagonal tile
        if (kt == qt) {
#pragma unroll
            for (int i = 0; i < 4; i++)
#pragma unroll
                for (int j = 0; j < 8; j++)
                    if (tx * 8 + j > ty * 4 + i) s[i][j] = -INFINITY;
        }

        // Online softmax (per-row stats reduced across the 8 tx lanes)
#pragma unroll
        for (int i = 0; i < 4; i++) {
            float mt = s[i][0];
#pragma unroll
            for (int j = 1; j < 8; j++) mt = fmaxf(mt, s[i][j]);
            mt = fmaxf(mt, __shfl_xor_sync(0xffffffffu, mt, 1));
            mt = fmaxf(mt, __shfl_xor_sync(0xffffffffu, mt, 2));
            mt = fmaxf(mt, __shfl_xor_sync(0xffffffffu, mt, 4));
            float mn = fmaxf(m[i], mt);
            float sc = __expf(m[i] - mn);
            float ps = 0.f;
#pragma unroll
            for (int j = 0; j < 8; j++) {
                float p = __expf(s[i][j] - mn);
                s[i][j] = p;
                ps += p;
            }
            ps += __shfl_xor_sync(0xffffffffu, ps, 1);
            ps += __shfl_xor_sync(0xffffffffu, ps, 2);
            ps += __shfl_xor_sync(0xffffffffu, ps, 4);
            l[i] = l[i] * sc + ps;
            m[i] = mn;
#pragma unroll
            for (int j = 0; j < 8; j++) {
                o[i][j] *= sc;
                Ps[(ty * 4 + i) * FSQ + tx * 8 + j] = s[i][j];
            }
        }
        __syncthreads();

        // O += P @ V
#pragma unroll 4
        for (int j = 0; j < 64; j++) {
            float p0 = Ps[(ty * 4 + 0) * FSQ + j];
            float p1 = Ps[(ty * 4 + 1) * FSQ + j];
            float p2 = Ps[(ty * 4 + 2) * FSQ + j];
            float p3 = Ps[(ty * 4 + 3) * FSQ + j];
            float vb[8];
            *(float4*)&vb[0] = *(const float4*)&Vs[j * FSV + tx * 8];
            *(float4*)&vb[4] = *(const float4*)&Vs[j * FSV + tx * 8 + 4];
#pragma unroll
            for (int jj = 0; jj < 8; jj++) {
                o[0][jj] = fmaf(p0, vb[jj], o[0][jj]);
                o[1][jj] = fmaf(p1, vb[jj], o[1][jj]);
                o[2][jj] = fmaf(p2, vb[jj], o[2][jj]);
                o[3][jj] = fmaf(p3, vb[jj], o[3][jj]);
            }
        }
    }

    // Normalize and write C (already in [b, t, h*HD + d] layout)
#pragma unroll
    for (int i = 0; i < 4; i++) {
        float inv = 1.f / l[i];
        float out[8];
#pragma unroll
        for (int j = 0; j < 8; j++) out[j] = o[i][j] * inv;
        float* Op = O + base + (size_t)(qt * 64 + ty * 4 + i) * D_ + tx * 8;
        *(float4*)&Op[0] = *(float4*)&out[0];
        *(float4*)&Op[4] = *(float4*)&out[4];
    }
}

// ---------------------------------------------------------------------------
extern "C" void kernel_launch(void* const* d_in, const int* in_sizes, int n_in,
                              void* d_out, int out_size)
{
    const float* X  = (const float*)d_in[0];
    const float* Wq = (const float*)d_in[1];
    const float* Wk = (const float*)d_in[2];
    const float* Wv = (const float*)d_in[3];
    const float* Wo = (const float*)d_in[4];
    const float* bo = (const float*)d_in[5];
    float* Y = (float*)d_out;

    float *gQ, *gK, *gV, *gC;
    cudaGetSymbolAddress((void**)&gQ, g_Q);
    cudaGetSymbolAddress((void**)&gK, g_K);
    cudaGetSymbolAddress((void**)&gV, g_V);
    cudaGetSymbolAddress((void**)&gC, g_C);

    cudaFuncSetAttribute(flash_kernel,
                         cudaFuncAttributeMaxDynamicSharedMemorySize,
                         FLASH_SMEM);

    dim3 gp(D_ / 128, M_ / 128);  // (8, 32)
    sgemm_kernel<<<gp, 256>>>(X, Wq, nullptr, gQ, M_, D_, D_);
    sgemm_kernel<<<gp, 256>>>(X, Wk, nullptr, gK, M_, D_, D_);
    sgemm_kernel<<<gp, 256>>>(X, Wv, nullptr, gV, M_, D_, D_);

    flash_kernel<<<dim3(T_ / 64, B_ * H_), 128, FLASH_SMEM>>>(gQ, gK, gV, gC);

    sgemm_kernel<<<gp, 256>>>(gC, Wo, bo, Y, M_, D_, D_);
}

// round 4
// speedup vs baseline: 1.3870x; 1.3870x over previous
#include <cuda_runtime.h>
#include <cuda_fp16.h>
#include <math.h>
#include <stdint.h>

// Problem shape (fixed)
#define B_  2
#define T_  2048
#define D_  1024
#define H_  16
#define HD_ 64
#define M_  (B_*T_)   // 4096

// ---------------------------------------------------------------------------
// Scratch (__device__ globals; no allocations allowed)
// ---------------------------------------------------------------------------
__device__ float g_Q[(size_t)M_ * D_];
__device__ float g_K[(size_t)M_ * D_];
__device__ float g_V[(size_t)M_ * D_];
__device__ float g_C[(size_t)M_ * D_];
__device__ __half g_XH[(size_t)M_ * D_];
__device__ __half g_XL[(size_t)M_ * D_];
__device__ __half g_CH[(size_t)M_ * D_];
__device__ __half g_CL[(size_t)M_ * D_];
// Transposed+split weights [N][K]: [0]=WqH [1]=WqL [2]=WkH [3]=WkL [4]=WvH [5]=WvL [6]=WoH [7]=WoL
__device__ __half g_WT16[8][(size_t)D_ * D_];

// ---------------------------------------------------------------------------
// PTX helpers (sm_80-level features only: valid at plain sm_100 target)
// ---------------------------------------------------------------------------
__device__ __forceinline__ uint32_t smem_u32(const void* p) {
    uint32_t a;
    asm("{ .reg .u64 t; cvta.to.shared.u64 t, %1; cvt.u32.u64 %0, t; }"
        : "=r"(a) : "l"(p));
    return a;
}

__device__ __forceinline__ void cp_async16(uint32_t saddr, const void* gaddr) {
    asm volatile("cp.async.cg.shared.global [%0], [%1], 16;"
                 :: "r"(saddr), "l"(gaddr));
}
#define CP_COMMIT() asm volatile("cp.async.commit_group;" ::: "memory")
#define CP_WAIT(n)  asm volatile("cp.async.wait_group %0;" :: "n"(n) : "memory")

__device__ __forceinline__ void ldm4(uint32_t* r, uint32_t addr) {
    asm volatile("ldmatrix.sync.aligned.m8n8.x4.shared.b16 {%0,%1,%2,%3}, [%4];"
                 : "=r"(r[0]), "=r"(r[1]), "=r"(r[2]), "=r"(r[3]) : "r"(addr));
}

__device__ __forceinline__ void mma16816(float* d, const uint32_t* a,
                                         uint32_t b0, uint32_t b1) {
    asm volatile(
        "mma.sync.aligned.m16n8k16.row.col.f32.f16.f16.f32 "
        "{%0,%1,%2,%3},{%4,%5,%6,%7},{%8,%9},{%0,%1,%2,%3};"
        : "+f"(d[0]), "+f"(d[1]), "+f"(d[2]), "+f"(d[3])
        : "r"(a[0]), "r"(a[1]), "r"(a[2]), "r"(a[3]), "r"(b0), "r"(b1));
}

__device__ __forceinline__ uint32_t h2_bits(__half2 v) {
    return *(uint32_t*)&v;
}

// ---------------------------------------------------------------------------
// Prepass 1: fp32 -> (fp16 hi, fp16 lo) split. lo = rn16(x - (float)hi).
// ---------------------------------------------------------------------------
__global__ void split16_kernel(const float4* __restrict__ in,
                               uint2* __restrict__ hi, uint2* __restrict__ lo,
                               int n4) {
    int i = blockIdx.x * blockDim.x + threadIdx.x;
    if (i >= n4) return;
    float4 v = in[i];
    __half hx = __float2half_rn(v.x), hy = __float2half_rn(v.y);
    __half hz = __float2half_rn(v.z), hw = __float2half_rn(v.w);
    __half lx = __float2half_rn(v.x - __half2float(hx));
    __half ly = __float2half_rn(v.y - __half2float(hy));
    __half lz = __float2half_rn(v.z - __half2float(hz));
    __half lw = __float2half_rn(v.w - __half2float(hw));
    __half2 h0 = __halves2half2(hx, hy), h1 = __halves2half2(hz, hw);
    __half2 l0 = __halves2half2(lx, ly), l1 = __halves2half2(lz, lw);
    hi[i] = make_uint2(h2_bits(h0), h2_bits(h1));
    lo[i] = make_uint2(h2_bits(l0), h2_bits(l1));
}

// ---------------------------------------------------------------------------
// Prepass 2: W[k][n] -> WT_hi[n][k], WT_lo[n][k] (transpose + fp16 split)
// ---------------------------------------------------------------------------
__global__ void transpose_split16_kernel(const float* __restrict__ W,
                                         __half* __restrict__ TH,
                                         __half* __restrict__ TL) {
    __shared__ float t[32][33];
    const int tx = threadIdx.x, ty = threadIdx.y;   // 32 x 8
    const int bn = blockIdx.x * 32;                  // n tile
    const int bk = blockIdx.y * 32;                  // k tile
#pragma unroll
    for (int i = 0; i < 4; i++)
        t[ty + 8 * i][tx] = W[(size_t)(bk + ty + 8 * i) * D_ + bn + tx];
    __syncthreads();
#pragma unroll
    for (int i = 0; i < 4; i++) {
        int row = ty + 8 * i;
        float v = t[tx][row];     // = W[bk+tx][bn+row]
        __half h = __float2half_rn(v);
        size_t o = (size_t)(bn + row) * D_ + bk + tx;
        TH[o] = h;
        TL[o] = __float2half_rn(v - __half2float(h));
    }
}

// ---------------------------------------------------------------------------
// mma.sync fp16 3-term GEMM: C[M,N] = A @ W, A=(AH,AL)[M,K] rm, B=(BH,BL)[N,K] rm.
// 128x128 block, 8 warps (2x4), warp tile 64x32, BK=32, 2-stage cp.async.
// smem rows padded to 80 B (conflict-free ldmatrix: r*20 mod 32 distinct).
// ---------------------------------------------------------------------------
#define G_TB     (128 * 80)          // one tile (128 rows x 80B)
#define G_STAGE  (4 * G_TB)          // Ah, Al, Bh, Bl
#define G_SMEM   (2 * G_STAGE)       // 81920 B
#define G_NK     32                   // K chunk
#define G_NCH    (D_ / G_NK)          // 32 chunks

__device__ __forceinline__ void g16_load(
    const __half* __restrict__ AH, const __half* __restrict__ AL,
    const __half* __restrict__ BH, const __half* __restrict__ BL,
    uint32_t sbase, int bm, int bn, int c, int tid)
{
    const int k0 = c * G_NK;
#pragma unroll
    for (int i = 0; i < 2; i++) {
        int idx = tid + (i << 8);
        int r = idx >> 2, ch = idx & 3;
        uint32_t so = (uint32_t)(r * 80 + ch * 16);
        size_t ga = (size_t)(bm + r) * D_ + k0 + ch * 8;
        size_t gb = (size_t)(bn + r) * D_ + k0 + ch * 8;
        cp_async16(sbase + so,            AH + ga);
        cp_async16(sbase + G_TB + so,     AL + ga);
        cp_async16(sbase + 2 * G_TB + so, BH + gb);
        cp_async16(sbase + 3 * G_TB + so, BL + gb);
    }
}

__global__ void __launch_bounds__(256, 1) gemm16_kernel(
    const __half* __restrict__ AH, const __half* __restrict__ AL,
    const __half* __restrict__ BH, const __half* __restrict__ BL,
    const float* __restrict__ bias, float* __restrict__ C)
{
    extern __shared__ char smem[];
    const uint32_t sb = smem_u32(smem);
    const int tid = threadIdx.x;
    const int lid = tid & 31;
    const int wid = tid >> 5;
    const int wm  = wid >> 2;       // 0..1
    const int wn  = wid & 3;        // 0..3
    const int row16 = lid & 15;
    const int sel   = lid >> 4;
    const int bm = blockIdx.y << 7;
    const int bn = blockIdx.x << 7;

    float acc[4][4][4];
#pragma unroll
    for (int mi = 0; mi < 4; mi++)
#pragma unroll
        for (int ni = 0; ni < 4; ni++)
#pragma unroll
            for (int j = 0; j < 4; j++) acc[mi][ni][j] = 0.f;

    g16_load(AH, AL, BH, BL, sb, bm, bn, 0, tid);
    CP_COMMIT();
    g16_load(AH, AL, BH, BL, sb + G_STAGE, bm, bn, 1, tid);
    CP_COMMIT();

    for (int c = 0; c < G_NCH; c++) {
        if (c < G_NCH - 1) CP_WAIT(1); else CP_WAIT(0);
        __syncthreads();

        const uint32_t s = sb + (uint32_t)(c & 1) * G_STAGE;
#pragma unroll
        for (int kk = 0; kk < 2; kk++) {
            const uint32_t koff = (uint32_t)((kk * 2 + sel) * 16);
            uint32_t ah[4][4], al[4][4];
#pragma unroll
            for (int mi = 0; mi < 4; mi++) {
                uint32_t addr = s + (uint32_t)((wm * 64 + mi * 16 + row16) * 80) + koff;
                ldm4(ah[mi], addr);
                ldm4(al[mi], addr + G_TB);
            }
            uint32_t bh[2][4], bl[2][4];
#pragma unroll
            for (int g = 0; g < 2; g++) {
                uint32_t addr = s + 2 * G_TB +
                                (uint32_t)((wn * 32 + g * 16 + row16) * 80) + koff;
                ldm4(bh[g], addr);
                ldm4(bl[g], addr + G_TB);
            }
#pragma unroll
            for (int mi = 0; mi < 4; mi++)
#pragma unroll
                for (int ni = 0; ni < 4; ni++) {
                    const int g = ni >> 1, o = ni & 1;
                    mma16816(acc[mi][ni], ah[mi], bh[g][o], bh[g][o + 2]);
                    mma16816(acc[mi][ni], ah[mi], bl[g][o], bl[g][o + 2]);
                    mma16816(acc[mi][ni], al[mi], bh[g][o], bh[g][o + 2]);
                }
        }
        __syncthreads();
        if (c + 2 < G_NCH) {
            g16_load(AH, AL, BH, BL, sb + (uint32_t)(c & 1) * G_STAGE,
                     bm, bn, c + 2, tid);
            CP_COMMIT();
        }
    }

    // Epilogue: C frag m16n8 -> rows (lid>>2)+{0,8}, cols (lid&3)*2+{0,1}
#pragma unroll
    for (int mi = 0; mi < 4; mi++)
#pragma unroll
        for (int ni = 0; ni < 4; ni++) {
            int row = bm + wm * 64 + mi * 16 + (lid >> 2);
            int col = bn + wn * 32 + ni * 8 + (lid & 3) * 2;
            float b0 = bias ? bias[col]     : 0.f;
            float b1 = bias ? bias[col + 1] : 0.f;
            float2 v0 = make_float2(acc[mi][ni][0] + b0, acc[mi][ni][1] + b1);
            float2 v1 = make_float2(acc[mi][ni][2] + b0, acc[mi][ni][3] + b1);
            *(float2*)&C[(size_t)row * D_ + col]       = v0;
            *(float2*)&C[(size_t)(row + 8) * D_ + col] = v1;
        }
}

// ---------------------------------------------------------------------------
// Flash attention (unchanged — verified correct, round 1)
// ---------------------------------------------------------------------------
#define FSQ 65
#define FSV 64
#define FLASH_SMEM ((3 * 64 * FSQ + 64 * FSV) * 4)

__global__ void __launch_bounds__(128) flash_kernel(
    const float* __restrict__ Q, const float* __restrict__ K,
    const float* __restrict__ V, float* __restrict__ O)
{
    extern __shared__ float sm[];
    float* Qs = sm;
    float* Ks = Qs + 64 * FSQ;
    float* Ps = Ks + 64 * FSQ;
    float* Vs = Ps + 64 * FSQ;

    const int qt  = blockIdx.x;
    const int bh  = blockIdx.y;
    const int b   = bh >> 4;
    const int h   = bh & 15;
    const int tid = threadIdx.x;
    const int tx  = tid & 7;
    const int ty  = tid >> 3;

    const size_t base = ((size_t)b * T_) * D_ + (size_t)h * HD_;

#pragma unroll
    for (int i = 0; i < 8; i++) {
        int idx = tid + (i << 7);
        int r = idx >> 4;
        int d = (idx & 15) << 2;
        float4 v = *(const float4*)(Q + base + (size_t)(qt * 64 + r) * D_ + d);
        float* p = &Qs[r * FSQ + d];
        p[0] = v.x * 0.125f; p[1] = v.y * 0.125f;
        p[2] = v.z * 0.125f; p[3] = v.w * 0.125f;
    }

    float o[4][8];
    float m[4], l[4];
#pragma unroll
    for (int i = 0; i < 4; i++) {
        m[i] = -INFINITY; l[i] = 0.f;
#pragma unroll
        for (int j = 0; j < 8; j++) o[i][j] = 0.f;
    }

    for (int kt = 0; kt <= qt; kt++) {
        __syncthreads();
#pragma unroll
        for (int i = 0; i < 8; i++) {
            int idx = tid + (i << 7);
            int r = idx >> 4;
            int d = (idx & 15) << 2;
            const size_t g = base + (size_t)(kt * 64 + r) * D_ + d;
            float4 kv = *(const float4*)(K + g);
            float* pk = &Ks[r * FSQ + d];
            pk[0] = kv.x; pk[1] = kv.y; pk[2] = kv.z; pk[3] = kv.w;
            *(float4*)&Vs[r * FSV + d] = *(const float4*)(V + g);
        }
        __syncthreads();

        float s[4][8];
#pragma unroll
        for (int i = 0; i < 4; i++)
#pragma unroll
            for (int j = 0; j < 8; j++) s[i][j] = 0.f;

#pragma unroll 4
        for (int d = 0; d < 64; d++) {
            float a0 = Qs[(ty * 4 + 0) * FSQ + d];
            float a1 = Qs[(ty * 4 + 1) * FSQ + d];
            float a2 = Qs[(ty * 4 + 2) * FSQ + d];
            float a3 = Qs[(ty * 4 + 3) * FSQ + d];
            float bb[8];
#pragma unroll
            for (int j = 0; j < 8; j++) bb[j] = Ks[(tx * 8 + j) * FSQ + d];
#pragma unroll
            for (int j = 0; j < 8; j++) {
                s[0][j] = fmaf(a0, bb[j], s[0][j]);
                s[1][j] = fmaf(a1, bb[j], s[1][j]);
                s[2][j] = fmaf(a2, bb[j], s[2][j]);
                s[3][j] = fmaf(a3, bb[j], s[3][j]);
            }
        }

        if (kt == qt) {
#pragma unroll
            for (int i = 0; i < 4; i++)
#pragma unroll
                for (int j = 0; j < 8; j++)
                    if (tx * 8 + j > ty * 4 + i) s[i][j] = -INFINITY;
        }

#pragma unroll
        for (int i = 0; i < 4; i++) {
            float mt = s[i][0];
#pragma unroll
            for (int j = 1; j < 8; j++) mt = fmaxf(mt, s[i][j]);
            mt = fmaxf(mt, __shfl_xor_sync(0xffffffffu, mt, 1));
            mt = fmaxf(mt, __shfl_xor_sync(0xffffffffu, mt, 2));
            mt = fmaxf(mt, __shfl_xor_sync(0xffffffffu, mt, 4));
            float mn = fmaxf(m[i], mt);
            float sc = __expf(m[i] - mn);
            float ps = 0.f;
#pragma unroll
            for (int j = 0; j < 8; j++) {
                float p = __expf(s[i][j] - mn);
                s[i][j] = p;
                ps += p;
            }
            ps += __shfl_xor_sync(0xffffffffu, ps, 1);
            ps += __shfl_xor_sync(0xffffffffu, ps, 2);
            ps += __shfl_xor_sync(0xffffffffu, ps, 4);
            l[i] = l[i] * sc + ps;
            m[i] = mn;
#pragma unroll
            for (int j = 0; j < 8; j++) {
                o[i][j] *= sc;
                Ps[(ty * 4 + i) * FSQ + tx * 8 + j] = s[i][j];
            }
        }
        __syncthreads();

#pragma unroll 4
        for (int j = 0; j < 64; j++) {
            float p0 = Ps[(ty * 4 + 0) * FSQ + j];
            float p1 = Ps[(ty * 4 + 1) * FSQ + j];
            float p2 = Ps[(ty * 4 + 2) * FSQ + j];
            float p3 = Ps[(ty * 4 + 3) * FSQ + j];
            float vb[8];
            *(float4*)&vb[0] = *(const float4*)&Vs[j * FSV + tx * 8];
            *(float4*)&vb[4] = *(const float4*)&Vs[j * FSV + tx * 8 + 4];
#pragma unroll
            for (int jj = 0; jj < 8; jj++) {
                o[0][jj] = fmaf(p0, vb[jj], o[0][jj]);
                o[1][jj] = fmaf(p1, vb[jj], o[1][jj]);
                o[2][jj] = fmaf(p2, vb[jj], o[2][jj]);
                o[3][jj] = fmaf(p3, vb[jj], o[3][jj]);
            }
        }
    }

#pragma unroll
    for (int i = 0; i < 4; i++) {
        float inv = 1.f / l[i];
        float out[8];
#pragma unroll
        for (int j = 0; j < 8; j++) out[j] = o[i][j] * inv;
        float* Op = O + base + (size_t)(qt * 64 + ty * 4 + i) * D_ + tx * 8;
        *(float4*)&Op[0] = *(float4*)&out[0];
        *(float4*)&Op[4] = *(float4*)&out[4];
    }
}

// ---------------------------------------------------------------------------
extern "C" void kernel_launch(void* const* d_in, const int* in_sizes, int n_in,
                              void* d_out, int out_size)
{
    const float* X  = (const float*)d_in[0];
    const float* Wq = (const float*)d_in[1];
    const float* Wk = (const float*)d_in[2];
    const float* Wv = (const float*)d_in[3];
    const float* Wo = (const float*)d_in[4];
    const float* bo = (const float*)d_in[5];
    float* Y = (float*)d_out;

    float *gQ, *gK, *gV, *gC;
    __half *gXH, *gXL, *gCH, *gCL, *gWT;
    cudaGetSymbolAddress((void**)&gQ,  g_Q);
    cudaGetSymbolAddress((void**)&gK,  g_K);
    cudaGetSymbolAddress((void**)&gV,  g_V);
    cudaGetSymbolAddress((void**)&gC,  g_C);
    cudaGetSymbolAddress((void**)&gXH, g_XH);
    cudaGetSymbolAddress((void**)&gXL, g_XL);
    cudaGetSymbolAddress((void**)&gCH, g_CH);
    cudaGetSymbolAddress((void**)&gCL, g_CL);
    cudaGetSymbolAddress((void**)&gWT, g_WT16);
    const size_t WSZ = (size_t)D_ * D_;

    cudaFuncSetAttribute(flash_kernel,
                         cudaFuncAttributeMaxDynamicSharedMemorySize, FLASH_SMEM);
    cudaFuncSetAttribute(gemm16_kernel,
                         cudaFuncAttributeMaxDynamicSharedMemorySize, G_SMEM);

    const int n4 = (M_ * D_) / 4;
    split16_kernel<<<(n4 + 255) / 256, 256>>>((const float4*)X,
                                              (uint2*)gXH, (uint2*)gXL, n4);
    dim3 tb(32, 8), tg(32, 32);
    transpose_split16_kernel<<<tg, tb>>>(Wq, gWT + 0 * WSZ, gWT + 1 * WSZ);
    transpose_split16_kernel<<<tg, tb>>>(Wk, gWT + 2 * WSZ, gWT + 3 * WSZ);
    transpose_split16_kernel<<<tg, tb>>>(Wv, gWT + 4 * WSZ, gWT + 5 * WSZ);
    transpose_split16_kernel<<<tg, tb>>>(Wo, gWT + 6 * WSZ, gWT + 7 * WSZ);

    dim3 gg(D_ / 128, M_ / 128);   // (8, 32)
    gemm16_kernel<<<gg, 256, G_SMEM>>>(gXH, gXL, gWT + 0 * WSZ, gWT + 1 * WSZ, nullptr, gQ);
    gemm16_kernel<<<gg, 256, G_SMEM>>>(gXH, gXL, gWT + 2 * WSZ, gWT + 3 * WSZ, nullptr, gK);
    gemm16_kernel<<<gg, 256, G_SMEM>>>(gXH, gXL, gWT + 4 * WSZ, gWT + 5 * WSZ, nullptr, gV);

    flash_kernel<<<dim3(T_ / 64, B_ * H_), 128, FLASH_SMEM>>>(gQ, gK, gV, gC);

    split16_kernel<<<(n4 + 255) / 256, 256>>>((const float4*)gC,
                                              (uint2*)gCH, (uint2*)gCL, n4);
    gemm16_kernel<<<gg, 256, G_SMEM>>>(gCH, gCL, gWT + 6 * WSZ, gWT + 7 * WSZ, bo, Y);
}

// round 5
// speedup vs baseline: 2.8974x; 2.0890x over previous
#include <cuda_runtime.h>
#include <cuda_fp16.h>
#include <math.h>
#include <stdint.h>

// Problem shape (fixed)
#define B_  2
#define T_  2048
#define D_  1024
#define H_  16
#define HD_ 64
#define M_  (B_*T_)   // 4096

// ---------------------------------------------------------------------------
// Scratch (__device__ globals; no allocations allowed)
// ---------------------------------------------------------------------------
__device__ __half g_XH[(size_t)M_ * D_];
__device__ __half g_XL[(size_t)M_ * D_];
__device__ __half g_QH[(size_t)M_ * D_];
__device__ __half g_QL[(size_t)M_ * D_];
__device__ __half g_KH[(size_t)M_ * D_];
__device__ __half g_KL[(size_t)M_ * D_];
__device__ __half g_VH[(size_t)M_ * D_];
__device__ __half g_VL[(size_t)M_ * D_];
__device__ __half g_CH[(size_t)M_ * D_];
__device__ __half g_CL[(size_t)M_ * D_];
// Transposed+split weights [N][K]: [0]=WqH [1]=WqL [2]=WkH [3]=WkL [4]=WvH [5]=WvL [6]=WoH [7]=WoL
__device__ __half g_WT16[8][(size_t)D_ * D_];

// ---------------------------------------------------------------------------
// PTX helpers (sm_80-level features only: valid at plain sm_100 target)
// ---------------------------------------------------------------------------
__device__ __forceinline__ uint32_t smem_u32(const void* p) {
    uint32_t a;
    asm("{ .reg .u64 t; cvta.to.shared.u64 t, %1; cvt.u32.u64 %0, t; }"
        : "=r"(a) : "l"(p));
    return a;
}

__device__ __forceinline__ void cp_async16(uint32_t saddr, const void* gaddr) {
    asm volatile("cp.async.cg.shared.global [%0], [%1], 16;"
                 :: "r"(saddr), "l"(gaddr));
}
#define CP_COMMIT() asm volatile("cp.async.commit_group;" ::: "memory")
#define CP_WAIT(n)  asm volatile("cp.async.wait_group %0;" :: "n"(n) : "memory")

__device__ __forceinline__ void ldm4(uint32_t* r, uint32_t addr) {
    asm volatile("ldmatrix.sync.aligned.m8n8.x4.shared.b16 {%0,%1,%2,%3}, [%4];"
                 : "=r"(r[0]), "=r"(r[1]), "=r"(r[2]), "=r"(r[3]) : "r"(addr));
}

__device__ __forceinline__ void ldm4t(uint32_t* r, uint32_t addr) {
    asm volatile("ldmatrix.sync.aligned.m8n8.x4.trans.shared.b16 {%0,%1,%2,%3}, [%4];"
                 : "=r"(r[0]), "=r"(r[1]), "=r"(r[2]), "=r"(r[3]) : "r"(addr));
}

__device__ __forceinline__ void mma16816(float* d, const uint32_t* a,
                                         uint32_t b0, uint32_t b1) {
    asm volatile(
        "mma.sync.aligned.m16n8k16.row.col.f32.f16.f16.f32 "
        "{%0,%1,%2,%3},{%4,%5,%6,%7},{%8,%9},{%0,%1,%2,%3};"
        : "+f"(d[0]), "+f"(d[1]), "+f"(d[2]), "+f"(d[3])
        : "r"(a[0]), "r"(a[1]), "r"(a[2]), "r"(a[3]), "r"(b0), "r"(b1));
}

__device__ __forceinline__ uint32_t h2_bits(__half2 v) {
    return *(uint32_t*)&v;
}

// ---------------------------------------------------------------------------
// Prepass 1: fp32 -> (fp16 hi, fp16 lo) split. lo = rn16(x - (float)hi).
// ---------------------------------------------------------------------------
__global__ void split16_kernel(const float4* __restrict__ in,
                               uint2* __restrict__ hi, uint2* __restrict__ lo,
                               int n4) {
    int i = blockIdx.x * blockDim.x + threadIdx.x;
    if (i >= n4) return;
    float4 v = in[i];
    __half hx = __float2half_rn(v.x), hy = __float2half_rn(v.y);
    __half hz = __float2half_rn(v.z), hw = __float2half_rn(v.w);
    __half lx = __float2half_rn(v.x - __half2float(hx));
    __half ly = __float2half_rn(v.y - __half2float(hy));
    __half lz = __float2half_rn(v.z - __half2float(hz));
    __half lw = __float2half_rn(v.w - __half2float(hw));
    __half2 h0 = __halves2half2(hx, hy), h1 = __halves2half2(hz, hw);
    __half2 l0 = __halves2half2(lx, ly), l1 = __halves2half2(lz, lw);
    hi[i] = make_uint2(h2_bits(h0), h2_bits(h1));
    lo[i] = make_uint2(h2_bits(l0), h2_bits(l1));
}

// ---------------------------------------------------------------------------
// Prepass 2: W[k][n] -> WT_hi[n][k], WT_lo[n][k] (transpose + fp16 split)
// ---------------------------------------------------------------------------
__global__ void transpose_split16_kernel(const float* __restrict__ W,
                                         __half* __restrict__ TH,
                                         __half* __restrict__ TL) {
    __shared__ float t[32][33];
    const int tx = threadIdx.x, ty = threadIdx.y;   // 32 x 8
    const int bn = blockIdx.x * 32;                  // n tile
    const int bk = blockIdx.y * 32;                  // k tile
#pragma unroll
    for (int i = 0; i < 4; i++)
        t[ty + 8 * i][tx] = W[(size_t)(bk + ty + 8 * i) * D_ + bn + tx];
    __syncthreads();
#pragma unroll
    for (int i = 0; i < 4; i++) {
        int row = ty + 8 * i;
        float v = t[tx][row];     // = W[bk+tx][bn+row]
        __half h = __float2half_rn(v);
        size_t o = (size_t)(bn + row) * D_ + bk + tx;
        TH[o] = h;
        TL[o] = __float2half_rn(v - __half2float(h));
    }
}

// ---------------------------------------------------------------------------
// mma.sync fp16 3-term GEMM: C[M,N] = A @ W, A=(AH,AL)[M,K] rm, B=(BH,BL)[N,K] rm.
// 128x128 block, 8 warps (2x4), warp tile 64x32, BK=32, 2-stage cp.async.
// Epilogue: either fp32 out (+bias) or split fp16 (hi,lo) out with scale.
// ---------------------------------------------------------------------------
#define G_TB     (128 * 80)
#define G_STAGE  (4 * G_TB)
#define G_SMEM   (2 * G_STAGE)       // 81920 B
#define G_NK     32
#define G_NCH    (D_ / G_NK)

__device__ __forceinline__ void g16_load(
    const __half* __restrict__ AH, const __half* __restrict__ AL,
    const __half* __restrict__ BH, const __half* __restrict__ BL,
    uint32_t sbase, int bm, int bn, int c, int tid)
{
    const int k0 = c * G_NK;
#pragma unroll
    for (int i = 0; i < 2; i++) {
        int idx = tid + (i << 8);
        int r = idx >> 2, ch = idx & 3;
        uint32_t so = (uint32_t)(r * 80 + ch * 16);
        size_t ga = (size_t)(bm + r) * D_ + k0 + ch * 8;
        size_t gb = (size_t)(bn + r) * D_ + k0 + ch * 8;
        cp_async16(sbase + so,            AH + ga);
        cp_async16(sbase + G_TB + so,     AL + ga);
        cp_async16(sbase + 2 * G_TB + so, BH + gb);
        cp_async16(sbase + 3 * G_TB + so, BL + gb);
    }
}

__global__ void __launch_bounds__(256, 1) gemm16_kernel(
    const __half* __restrict__ AH, const __half* __restrict__ AL,
    const __half* __restrict__ BH, const __half* __restrict__ BL,
    const float* __restrict__ bias, float scale,
    float* __restrict__ outF,
    __half* __restrict__ outH, __half* __restrict__ outL)
{
    extern __shared__ char smem[];
    const uint32_t sb = smem_u32(smem);
    const int tid = threadIdx.x;
    const int lid = tid & 31;
    const int wid = tid >> 5;
    const int wm  = wid >> 2;
    const int wn  = wid & 3;
    const int row16 = lid & 15;
    const int sel   = lid >> 4;
    const int bm = blockIdx.y << 7;
    const int bn = blockIdx.x << 7;

    float acc[4][4][4];
#pragma unroll
    for (int mi = 0; mi < 4; mi++)
#pragma unroll
        for (int ni = 0; ni < 4; ni++)
#pragma unroll
            for (int j = 0; j < 4; j++) acc[mi][ni][j] = 0.f;

    g16_load(AH, AL, BH, BL, sb, bm, bn, 0, tid);
    CP_COMMIT();
    g16_load(AH, AL, BH, BL, sb + G_STAGE, bm, bn, 1, tid);
    CP_COMMIT();

    for (int c = 0; c < G_NCH; c++) {
        if (c < G_NCH - 1) CP_WAIT(1); else CP_WAIT(0);
        __syncthreads();

        const uint32_t s = sb + (uint32_t)(c & 1) * G_STAGE;
#pragma unroll
        for (int kk = 0; kk < 2; kk++) {
            const uint32_t koff = (uint32_t)((kk * 2 + sel) * 16);
            uint32_t ah[4][4], al[4][4];
#pragma unroll
            for (int mi = 0; mi < 4; mi++) {
                uint32_t addr = s + (uint32_t)((wm * 64 + mi * 16 + row16) * 80) + koff;
                ldm4(ah[mi], addr);
                ldm4(al[mi], addr + G_TB);
            }
            uint32_t bh[2][4], bl[2][4];
#pragma unroll
            for (int g = 0; g < 2; g++) {
                uint32_t addr = s + 2 * G_TB +
                                (uint32_t)((wn * 32 + g * 16 + row16) * 80) + koff;
                ldm4(bh[g], addr);
                ldm4(bl[g], addr + G_TB);
            }
#pragma unroll
            for (int mi = 0; mi < 4; mi++)
#pragma unroll
                for (int ni = 0; ni < 4; ni++) {
                    const int g = ni >> 1, o = ni & 1;
                    mma16816(acc[mi][ni], ah[mi], bh[g][o], bh[g][o + 2]);
                    mma16816(acc[mi][ni], ah[mi], bl[g][o], bl[g][o + 2]);
                    mma16816(acc[mi][ni], al[mi], bh[g][o], bh[g][o + 2]);
                }
        }
        __syncthreads();
        if (c + 2 < G_NCH) {
            g16_load(AH, AL, BH, BL, sb + (uint32_t)(c & 1) * G_STAGE,
                     bm, bn, c + 2, tid);
            CP_COMMIT();
        }
    }

#pragma unroll
    for (int mi = 0; mi < 4; mi++)
#pragma unroll
        for (int ni = 0; ni < 4; ni++) {
            int row = bm + wm * 64 + mi * 16 + (lid >> 2);
            int col = bn + wn * 32 + ni * 8 + (lid & 3) * 2;
            float v0 = acc[mi][ni][0] * scale, v1 = acc[mi][ni][1] * scale;
            float v2 = acc[mi][ni][2] * scale, v3 = acc[mi][ni][3] * scale;
            if (outF) {
                float b0 = bias ? bias[col] : 0.f, b1 = bias ? bias[col + 1] : 0.f;
                *(float2*)&outF[(size_t)row * D_ + col]       = make_float2(v0 + b0, v1 + b1);
                *(float2*)&outF[(size_t)(row + 8) * D_ + col] = make_float2(v2 + b0, v3 + b1);
            } else {
                __half2 h0 = __floats2half2_rn(v0, v1);
                __half2 l0 = __floats2half2_rn(v0 - __low2float(h0), v1 - __high2float(h0));
                __half2 h1 = __floats2half2_rn(v2, v3);
                __half2 l1 = __floats2half2_rn(v2 - __low2float(h1), v3 - __high2float(h1));
                *(__half2*)&outH[(size_t)row * D_ + col]       = h0;
                *(__half2*)&outL[(size_t)row * D_ + col]       = l0;
                *(__half2*)&outH[(size_t)(row + 8) * D_ + col] = h1;
                *(__half2*)&outL[(size_t)(row + 8) * D_ + col] = l1;
            }
        }
}

// ---------------------------------------------------------------------------
// Flash attention v2: mma.sync fp16 split-precision, causal, online softmax.
// Block: 64 q-rows of one (b,h); 4 warps x 16 rows. K-tiles of 64.
// S = QhKh + QhKl + QlKh (fp32 acc); PV = PhVh + PhVl + PlVh.
// Smem rows padded to 144 B (64 halves + 16) for conflict-free ldmatrix.
// ---------------------------------------------------------------------------
#define F_QTILE 9216                       // 64 * 144
#define F_STAGE (4 * F_QTILE)              // Kh, Kl, Vh, Vl
#define F_SMEM  (2 * F_QTILE + 2 * F_STAGE)  // 92160

__device__ __forceinline__ void f_load_kv(
    const __half* __restrict__ KH, const __half* __restrict__ KL,
    const __half* __restrict__ VH, const __half* __restrict__ VL,
    uint32_t sbase, size_t base, int kt, int tid)
{
#pragma unroll
    for (int i = 0; i < 16; i++) {
        const __half* src = (i < 4) ? KH : (i < 8) ? KL : (i < 12) ? VH : VL;
        int tile = i >> 2;
        int r = (tid >> 3) + (i & 3) * 16;
        uint32_t sa = sbase + (uint32_t)(tile * F_QTILE + r * 144 + (tid & 7) * 16);
        cp_async16(sa, src + base + (size_t)(kt * 64 + r) * D_ + (tid & 7) * 8);
    }
}

__global__ void __launch_bounds__(128) flash16_kernel(
    const __half* __restrict__ QH, const __half* __restrict__ QL,
    const __half* __restrict__ KH, const __half* __restrict__ KL,
    const __half* __restrict__ VH, const __half* __restrict__ VL,
    __half* __restrict__ CH, __half* __restrict__ CL)
{
    extern __shared__ char fsm[];
    const uint32_t sb = smem_u32(fsm);
    const int qt = blockIdx.x;
    const int bh = blockIdx.y;
    const int b = bh >> 4, h = bh & 15;
    const int tid = threadIdx.x, wid = tid >> 5, lid = tid & 31;
    const size_t base = ((size_t)b * T_) * D_ + (size_t)h * HD_;

    // Q tiles -> smem (group A together with KV stage 0)
#pragma unroll
    for (int i = 0; i < 8; i++) {
        const __half* src = (i < 4) ? QH : QL;
        int r = (tid >> 3) + (i & 3) * 16;
        uint32_t sa = sb + (uint32_t)((i < 4 ? 0 : F_QTILE) + r * 144 + (tid & 7) * 16);
        cp_async16(sa, src + base + (size_t)(qt * 64 + r) * D_ + (tid & 7) * 8);
    }
    f_load_kv(KH, KL, VH, VL, sb + 2 * F_QTILE, base, 0, tid);
    CP_COMMIT();
    if (qt >= 1) {
        f_load_kv(KH, KL, VH, VL, sb + 2 * F_QTILE + F_STAGE, base, 1, tid);
        CP_COMMIT();
    }

    uint32_t qfh[4][4], qfl[4][4];
    float oacc[8][4];
    float m_[2] = {-INFINITY, -INFINITY}, l_[2] = {0.f, 0.f};
#pragma unroll
    for (int ni = 0; ni < 8; ni++)
#pragma unroll
        for (int j = 0; j < 4; j++) oacc[ni][j] = 0.f;

    for (int kt = 0; kt <= qt; kt++) {
        if (kt < qt) CP_WAIT(1); else CP_WAIT(0);
        __syncthreads();

        if (kt == 0) {
#pragma unroll
            for (int dc = 0; dc < 4; dc++) {
                uint32_t a = sb + (uint32_t)((wid * 16 + (lid & 15)) * 144
                             + dc * 32 + (lid >> 4) * 16);
                ldm4(qfh[dc], a);
                ldm4(qfl[dc], a + F_QTILE);
            }
        }

        const uint32_t ks = sb + 2 * F_QTILE + (uint32_t)(kt & 1) * F_STAGE;

        // ---- S = Q K^T (3-term) ----
        float sacc[8][4];
#pragma unroll
        for (int ni = 0; ni < 8; ni++)
#pragma unroll
            for (int j = 0; j < 4; j++) sacc[ni][j] = 0.f;

#pragma unroll
        for (int dc = 0; dc < 4; dc++) {
#pragma unroll
            for (int g = 0; g < 4; g++) {
                uint32_t ka = ks + (uint32_t)((g * 16 + (lid & 7) + ((lid >> 4) & 1) * 8) * 144
                              + dc * 32 + ((lid >> 3) & 1) * 16);
                uint32_t kh4[4], kl4[4];
                ldm4(kh4, ka);
                ldm4(kl4, ka + F_QTILE);
                mma16816(sacc[2 * g],     qfh[dc], kh4[0], kh4[1]);
                mma16816(sacc[2 * g],     qfh[dc], kl4[0], kl4[1]);
                mma16816(sacc[2 * g],     qfl[dc], kh4[0], kh4[1]);
                mma16816(sacc[2 * g + 1], qfh[dc], kh4[2], kh4[3]);
                mma16816(sacc[2 * g + 1], qfh[dc], kl4[2], kl4[3]);
                mma16816(sacc[2 * g + 1], qfl[dc], kh4[2], kh4[3]);
            }
        }

        // ---- causal mask (diagonal tile) ----
        if (kt == qt) {
            int r0 = wid * 16 + (lid >> 2);
#pragma unroll
            for (int ni = 0; ni < 8; ni++) {
                int c0 = ni * 8 + (lid & 3) * 2;
                if (c0     > r0)     sacc[ni][0] = -INFINITY;
                if (c0 + 1 > r0)     sacc[ni][1] = -INFINITY;
                if (c0     > r0 + 8) sacc[ni][2] = -INFINITY;
                if (c0 + 1 > r0 + 8) sacc[ni][3] = -INFINITY;
            }
        }

        // ---- online softmax ----
#pragma unroll
        for (int r = 0; r < 2; r++) {
            float mt = -INFINITY;
#pragma unroll
            for (int ni = 0; ni < 8; ni++)
                mt = fmaxf(mt, fmaxf(sacc[ni][2 * r], sacc[ni][2 * r + 1]));
            mt = fmaxf(mt, __shfl_xor_sync(0xffffffffu, mt, 1));
            mt = fmaxf(mt, __shfl_xor_sync(0xffffffffu, mt, 2));
            float mn = fmaxf(m_[r], mt);
            float sc = __expf(m_[r] - mn);
            float ps = 0.f;
#pragma unroll
            for (int ni = 0; ni < 8; ni++) {
                float p0 = __expf(sacc[ni][2 * r]     - mn);
                float p1 = __expf(sacc[ni][2 * r + 1] - mn);
                sacc[ni][2 * r] = p0; sacc[ni][2 * r + 1] = p1;
                ps += p0 + p1;
            }
            ps += __shfl_xor_sync(0xffffffffu, ps, 1);
            ps += __shfl_xor_sync(0xffffffffu, ps, 2);
            l_[r] = l_[r] * sc + ps;
            m_[r] = mn;
#pragma unroll
            for (int ni = 0; ni < 8; ni++) {
                oacc[ni][2 * r]     *= sc;
                oacc[ni][2 * r + 1] *= sc;
            }
        }

        // ---- pack P into A-fragments (hi + lo) ----
        uint32_t pah[4][4], pal[4][4];
#pragma unroll
        for (int kc = 0; kc < 4; kc++) {
#pragma unroll
            for (int q = 0; q < 4; q++) {
                int ni = 2 * kc + (q >> 1);
                float p0 = sacc[ni][(q & 1) * 2];
                float p1 = sacc[ni][(q & 1) * 2 + 1];
                __half2 hp = __floats2half2_rn(p0, p1);
                __half2 lp = __floats2half2_rn(p0 - __low2float(hp),
                                               p1 - __high2float(hp));
                pah[kc][q] = h2_bits(hp);
                pal[kc][q] = h2_bits(lp);
            }
        }

        // ---- O += P V (3-term) ----
        const uint32_t vs = ks + 2 * F_QTILE;
#pragma unroll
        for (int kc = 0; kc < 4; kc++) {
#pragma unroll
            for (int g = 0; g < 4; g++) {
                uint32_t va = vs + (uint32_t)((kc * 16 + (lid & 7) + ((lid >> 3) & 1) * 8) * 144
                              + (g * 16 + ((lid >> 4) & 1) * 8) * 2);
                uint32_t vh4[4], vl4[4];
                ldm4t(vh4, va);
                ldm4t(vl4, va + F_QTILE);
                mma16816(oacc[2 * g],     pah[kc], vh4[0], vh4[1]);
                mma16816(oacc[2 * g],     pah[kc], vl4[0], vl4[1]);
                mma16816(oacc[2 * g],     pal[kc], vh4[0], vh4[1]);
                mma16816(oacc[2 * g + 1], pah[kc], vh4[2], vh4[3]);
                mma16816(oacc[2 * g + 1], pah[kc], vl4[2], vl4[3]);
                mma16816(oacc[2 * g + 1], pal[kc], vh4[2], vh4[3]);
            }
        }

        __syncthreads();
        if (kt + 2 <= qt) {
            f_load_kv(KH, KL, VH, VL, sb + 2 * F_QTILE + (uint32_t)(kt & 1) * F_STAGE,
                      base, kt + 2, tid);
            CP_COMMIT();
        }
    }

    // ---- epilogue: normalize and write split C ----
    float inv0 = 1.f / l_[0], inv1 = 1.f / l_[1];
    int row0 = qt * 64 + wid * 16 + (lid >> 2);
#pragma unroll
    for (int ni = 0; ni < 8; ni++) {
        int col = ni * 8 + (lid & 3) * 2;
        float v0 = oacc[ni][0] * inv0, v1 = oacc[ni][1] * inv0;
        float v2 = oacc[ni][2] * inv1, v3 = oacc[ni][3] * inv1;
        __half2 h0 = __floats2half2_rn(v0, v1);
        __half2 l0 = __floats2half2_rn(v0 - __low2float(h0), v1 - __high2float(h0));
        __half2 h1 = __floats2half2_rn(v2, v3);
        __half2 l1 = __floats2half2_rn(v2 - __low2float(h1), v3 - __high2float(h1));
        size_t o0 = base + (size_t)row0 * D_ + col;
        size_t o1 = base + (size_t)(row0 + 8) * D_ + col;
        *(__half2*)&CH[o0] = h0;
        *(__half2*)&CL[o0] = l0;
        *(__half2*)&CH[o1] = h1;
        *(__half2*)&CL[o1] = l1;
    }
}

// ---------------------------------------------------------------------------
extern "C" void kernel_launch(void* const* d_in, const int* in_sizes, int n_in,
                              void* d_out, int out_size)
{
    const float* X  = (const float*)d_in[0];
    const float* Wq = (const float*)d_in[1];
    const float* Wk = (const float*)d_in[2];
    const float* Wv = (const float*)d_in[3];
    const float* Wo = (const float*)d_in[4];
    const float* bo = (const float*)d_in[5];
    float* Y = (float*)d_out;

    __half *gXH, *gXL, *gQH, *gQL, *gKH, *gKL, *gVH, *gVL, *gCH, *gCL, *gWT;
    cudaGetSymbolAddress((void**)&gXH, g_XH);
    cudaGetSymbolAddress((void**)&gXL, g_XL);
    cudaGetSymbolAddress((void**)&gQH, g_QH);
    cudaGetSymbolAddress((void**)&gQL, g_QL);
    cudaGetSymbolAddress((void**)&gKH, g_KH);
    cudaGetSymbolAddress((void**)&gKL, g_KL);
    cudaGetSymbolAddress((void**)&gVH, g_VH);
    cudaGetSymbolAddress((void**)&gVL, g_VL);
    cudaGetSymbolAddress((void**)&gCH, g_CH);
    cudaGetSymbolAddress((void**)&gCL, g_CL);
    cudaGetSymbolAddress((void**)&gWT, g_WT16);
    const size_t WSZ = (size_t)D_ * D_;

    cudaFuncSetAttribute(gemm16_kernel,
                         cudaFuncAttributeMaxDynamicSharedMemorySize, G_SMEM);
    cudaFuncSetAttribute(flash16_kernel,
                         cudaFuncAttributeMaxDynamicSharedMemorySize, F_SMEM);

    const int n4 = (M_ * D_) / 4;
    split16_kernel<<<(n4 + 255) / 256, 256>>>((const float4*)X,
                                              (uint2*)gXH, (uint2*)gXL, n4);
    dim3 tb(32, 8), tg(32, 32);
    transpose_split16_kernel<<<tg, tb>>>(Wq, gWT + 0 * WSZ, gWT + 1 * WSZ);
    transpose_split16_kernel<<<tg, tb>>>(Wk, gWT + 2 * WSZ, gWT + 3 * WSZ);
    transpose_split16_kernel<<<tg, tb>>>(Wv, gWT + 4 * WSZ, gWT + 5 * WSZ);
    transpose_split16_kernel<<<tg, tb>>>(Wo, gWT + 6 * WSZ, gWT + 7 * WSZ);

    dim3 gg(D_ / 128, M_ / 128);   // (8, 32)
    // Q projection carries the 1/sqrt(HD) = 0.125 scale (exact: (-inf)/8 == -inf)
    gemm16_kernel<<<gg, 256, G_SMEM>>>(gXH, gXL, gWT + 0 * WSZ, gWT + 1 * WSZ,
                                       nullptr, 0.125f, nullptr, gQH, gQL);
    gemm16_kernel<<<gg, 256, G_SMEM>>>(gXH, gXL, gWT + 2 * WSZ, gWT + 3 * WSZ,
                                       nullptr, 1.0f, nullptr, gKH, gKL);
    gemm16_kernel<<<gg, 256, G_SMEM>>>(gXH, gXL, gWT + 4 * WSZ, gWT + 5 * WSZ,
                                       nullptr, 1.0f, nullptr, gVH, gVL);

    flash16_kernel<<<dim3(T_ / 64, B_ * H_), 128, F_SMEM>>>(
        gQH, gQL, gKH, gKL, gVH, gVL, gCH, gCL);

    gemm16_kernel<<<gg, 256, G_SMEM>>>(gCH, gCL, gWT + 6 * WSZ, gWT + 7 * WSZ,
                                       bo, 1.0f, Y, nullptr, nullptr);
}